// round 6
// baseline (speedup 1.0000x reference)
#include <cuda_runtime.h>
#include <stdint.h>
#include <math.h>

// Problem constants
#define B_TOTAL 8192
#define T_STEPS 60
#define F_IN    158
#define HDIM    32
#define G4      128
#define NBLK    128                    // 64-row batch tiles
#define KP      79                     // k-pairs covering F_IN
#define TPAIRS  30                     // timestep pairs

typedef unsigned long long u64;
typedef ulonglong2 u64x2;

// 251.7 MB scratch: xg[tile][m(64)][n(128)], tile = t*NBLK + blk
__device__ __align__(256) float g_xg[(size_t)T_STEPS * NBLK * 64 * G4];

// ---------------- helpers ----------------
__device__ __forceinline__ void ffma2(u64 &acc, u64 a, u64 b) {
    asm("fma.rn.f32x2 %0, %1, %2, %0;" : "+l"(acc) : "l"(a), "l"(b));
}
__device__ __forceinline__ u64 pack2(float x, float y) {
    u64 r; asm("mov.b64 %0, {%1, %2};" : "=l"(r) : "f"(x), "f"(y)); return r;
}
__device__ __forceinline__ float2 unpack2(u64 v) {
    float2 r; asm("mov.b64 {%0, %1}, %2;" : "=f"(r.x), "=f"(r.y) : "l"(v)); return r;
}
__device__ __forceinline__ float sigf(float x) {
    float e = __expf(-x);
    return __fdividef(1.0f, 1.0f + e);
}
__device__ __forceinline__ float tanhf_(float x) {
    float ax = fabsf(x);
    float e = __expf(-2.0f * ax);
    float t = __fdividef(1.0f - e, 1.0f + e);
    return copysignf(t, x);
}
__device__ __forceinline__ void cp_async16(uint32_t dst, const void* src) {
    asm volatile("cp.async.cg.shared.global [%0], [%1], 16;" :: "r"(dst), "l"(src));
}
__device__ __forceinline__ void cp_commit() { asm volatile("cp.async.commit_group;"); }
__device__ __forceinline__ void cp_wait1()  { asm volatile("cp.async.wait_group 1;" ::: "memory"); }

// =======================================================================
// Kernel A: xg = x @ W_ih0^T, timestep-PAIR items.
//   item = (tp, blk, half): rows blk*64+half*32 .. +32, timesteps 2tp,2tp+1.
//   x smem row: 316 floats (both timesteps, contiguous in gmem, 16B-aligned
//   source) + 4 pad = 320. One weight fetch feeds both timesteps.
//   k-pair split accumulators (even-k, odd-k halves), folded at the end.
// =======================================================================
#define A_THREADS 256
#define A_ROWS    32
#define A_XROW    320
#define A_XBUF    (A_ROWS * A_XROW)        // 10240 floats
#define A_ITEMS   (TPAIRS * NBLK * 2)      // 7680
#define A_SW_U64  (KP * G4)                // 10112 u64 = 80896 B
#define A_SMEM_BYTES (A_SW_U64 * 8 + 2 * A_XBUF * 4)   // 162816 B

__device__ __forceinline__ void a_copy_item(const float* __restrict__ x,
                                            int item, float* xbuf, int tid) {
    int tp = item >> 8;
    int rem = item & 255;
    int blk = rem >> 1, half = rem & 1;
    const char* sb = (const char*)x
        + (size_t)(blk * 64 + half * 32) * (F_IN * T_STEPS * 4)
        + (size_t)tp * 1264;                       // 2*158*4 bytes, 16B aligned
    uint32_t db = (uint32_t)__cvta_generic_to_shared(xbuf);
    for (int i = tid; i < A_ROWS * KP; i += A_THREADS) {
        int r = i / KP, c = i - r * KP;            // 79 x 16B chunks = 316 floats
        cp_async16(db + r * (A_XROW * 4) + 16 * c,
                   sb + (size_t)r * (F_IN * T_STEPS * 4) + 16 * c);
    }
}

__global__ void __launch_bounds__(A_THREADS)
xg_kernel(const float* __restrict__ x, const float* __restrict__ Wih0) {
    extern __shared__ char smraw[];
    u64*   sWp = (u64*)smraw;                      // [kp][lane][4] = (W[n][2kp],W[n][2kp+1])
    float* xb  = (float*)(smraw + A_SW_U64 * 8);   // [2][32][320]

    const int tid = threadIdx.x;
    const int lane = tid & 31, wrp = tid >> 5;
    const int r0 = wrp * 4;                        // 8 warps x 4 rows

    for (int i = tid; i < KP * G4; i += A_THREADS) {
        int kp = i >> 7, n = i & 127;
        int j = n & 31, g = n >> 5;
        sWp[(kp * 32 + j) * 4 + g] = *(const u64*)(Wih0 + n * F_IN + 2 * kp);
    }

    int item = blockIdx.x;
    a_copy_item(x, item, xb, tid);
    cp_commit();

    int cur = 0;
    for (; item < A_ITEMS; item += gridDim.x) {
        int nxt = item + gridDim.x;
        if (nxt < A_ITEMS) a_copy_item(x, nxt, xb + (cur ^ 1) * A_XBUF, tid);
        cp_commit();
        cp_wait1();
        __syncthreads();           // current x buffer resident, weights loaded

        const float* xbase = xb + cur * A_XBUF + r0 * A_XROW;

        u64 acc[2][4][4];          // [tile][g][row], k-parity split in the u64
#pragma unroll
        for (int ti = 0; ti < 2; ++ti)
#pragma unroll
            for (int g = 0; g < 4; ++g)
#pragma unroll
                for (int q = 0; q < 4; ++q) acc[ti][g][q] = 0ULL;

#pragma unroll 1
        for (int kp2 = 0; kp2 < 39; ++kp2) {       // kp = 2*kp2, 2*kp2+1
            const float* xk = xbase + 4 * kp2;
            u64 x0a[4], x0b[4], x1a[4], x1b[4];
#pragma unroll
            for (int q = 0; q < 4; ++q) {
                u64x2 v = *(const u64x2*)(xk + q * A_XROW);        // tile0 kp,kp+1
                x0a[q] = v.x; x0b[q] = v.y;
                x1a[q] = *(const u64*)(xk + q * A_XROW + 158);     // tile1 kp
                x1b[q] = *(const u64*)(xk + q * A_XROW + 160);     // tile1 kp+1
            }
            const u64* wp = sWp + ((2 * kp2) * 32 + lane) * 4;
            u64x2 wa = *(const u64x2*)wp;           // kp:   g0,g1
            u64x2 wb = *(const u64x2*)(wp + 2);     // kp:   g2,g3
            u64x2 wc = *(const u64x2*)(wp + 128);   // kp+1: g0,g1
            u64x2 wd = *(const u64x2*)(wp + 130);   // kp+1: g2,g3
#pragma unroll
            for (int q = 0; q < 4; ++q) {
                ffma2(acc[0][0][q], x0a[q], wa.x);
                ffma2(acc[0][1][q], x0a[q], wa.y);
                ffma2(acc[0][2][q], x0a[q], wb.x);
                ffma2(acc[0][3][q], x0a[q], wb.y);
                ffma2(acc[0][0][q], x0b[q], wc.x);
                ffma2(acc[0][1][q], x0b[q], wc.y);
                ffma2(acc[0][2][q], x0b[q], wd.x);
                ffma2(acc[0][3][q], x0b[q], wd.y);
                ffma2(acc[1][0][q], x1a[q], wa.x);
                ffma2(acc[1][1][q], x1a[q], wa.y);
                ffma2(acc[1][2][q], x1a[q], wb.x);
                ffma2(acc[1][3][q], x1a[q], wb.y);
                ffma2(acc[1][0][q], x1b[q], wc.x);
                ffma2(acc[1][1][q], x1b[q], wc.y);
                ffma2(acc[1][2][q], x1b[q], wd.x);
                ffma2(acc[1][3][q], x1b[q], wd.y);
            }
        }
        {   // tail kp = 78
            const float* xk = xbase + 156;
            const u64* wp = sWp + (78 * 32 + lane) * 4;
            u64x2 wa = *(const u64x2*)wp;
            u64x2 wb = *(const u64x2*)(wp + 2);
#pragma unroll
            for (int q = 0; q < 4; ++q) {
                u64 x0 = *(const u64*)(xk + q * A_XROW);
                u64 x1 = *(const u64*)(xk + q * A_XROW + 158);
                ffma2(acc[0][0][q], x0, wa.x);
                ffma2(acc[0][1][q], x0, wa.y);
                ffma2(acc[0][2][q], x0, wb.x);
                ffma2(acc[0][3][q], x0, wb.y);
                ffma2(acc[1][0][q], x1, wa.x);
                ffma2(acc[1][1][q], x1, wa.y);
                ffma2(acc[1][2][q], x1, wb.x);
                ffma2(acc[1][3][q], x1, wb.y);
            }
        }

        // fold k-parity halves, direct coalesced STG.32
        {
            int tp = item >> 8;
            int rem = item & 255;
            int blk = rem >> 1, half = rem & 1;
#pragma unroll
            for (int ti = 0; ti < 2; ++ti) {
                int t = 2 * tp + ti;
                float* dst = g_xg + ((size_t)t * NBLK + blk) * (64 * G4)
                                  + (size_t)(half * 32 + r0) * G4 + lane;
#pragma unroll
                for (int q = 0; q < 4; ++q)
#pragma unroll
                    for (int g = 0; g < 4; ++g) {
                        float2 v = unpack2(acc[ti][g][q]);
                        dst[q * G4 + 32 * g] = v.x + v.y;
                    }
            }
        }
        __syncthreads();           // everyone done reading xb[cur] before overwrite
        cur ^= 1;
    }
}

// =======================================================================
// Kernel B: recurrence. 512 threads, 4 rows/warp (warp-private h state,
// no block barriers in the loop). Weights pre-dup'd f32x2 in [k][j][4]u64
// layout -> LDS.128; h loads LDS.128 broadcast.
// =======================================================================
#define B_THREADS 512
#define HPAD 68
#define B_SW_U64 (HDIM * G4)                   // 4096 u64 = 32 KB per matrix
#define B_SMEM_BYTES (3 * B_SW_U64 * 8 + 2 * HDIM * HPAD * 4)   // 115712 B

__global__ void __launch_bounds__(B_THREADS)
lstm_rec_kernel(const float* __restrict__ Whh0, const float* __restrict__ Wih1,
                const float* __restrict__ Whh1, const float* __restrict__ W1,
                const float* __restrict__ b1,   const float* __restrict__ W2,
                float* __restrict__ out) {
    extern __shared__ char smraw[];
    u64* sW0 = (u64*)smraw;                         // Whh0 [k][j][4] dup'd
    u64* sW1 = sW0 + B_SW_U64;                      // Wih1
    u64* sW2 = sW1 + B_SW_U64;                      // Whh1
    float* h1 = (float*)(sW2 + B_SW_U64);           // [32][68]
    float* h2 = h1 + HDIM * HPAD;

    const int tid = threadIdx.x;
    const int j = tid & 31, wrp = tid >> 5;
    const int m0 = wrp * 4;                         // 16 warps x 4 rows
    const int blk = blockIdx.x;

    for (int i = tid; i < HDIM * G4; i += B_THREADS) {
        int k = i >> 7, n = i & 127;
        int jj = n & 31, g = n >> 5;
        float w0 = Whh0[n * HDIM + k];
        float w1 = Wih1[n * HDIM + k];
        float w2 = Whh1[n * HDIM + k];
        sW0[(k * 32 + jj) * 4 + g] = pack2(w0, w0);
        sW1[(k * 32 + jj) * 4 + g] = pack2(w1, w1);
        sW2[(k * 32 + jj) * 4 + g] = pack2(w2, w2);
    }
    for (int i = tid; i < 2 * HDIM * HPAD; i += B_THREADS) h1[i] = 0.0f;
    __syncthreads();

    float c1[4] = {0.f, 0.f, 0.f, 0.f};
    float c2[4] = {0.f, 0.f, 0.f, 0.f};

    for (int t = 0; t < T_STEPS; ++t) {
        // coalesced xg prefetch for this step (consumed after the gemm)
        const float* xt = g_xg + ((size_t)t * NBLK + blk) * (64 * G4);
        float xr[4][4];                             // [g][row]
#pragma unroll
        for (int g = 0; g < 4; ++g)
#pragma unroll
            for (int q = 0; q < 4; ++q)
                xr[g][q] = __ldg(xt + (m0 + q) * G4 + j + 32 * g);

        // ---- layer 1: acc = h1 @ Whh0^T ----
        u64 acc[4][2];                              // [g][rowpair]
#pragma unroll
        for (int g = 0; g < 4; ++g) { acc[g][0] = 0ULL; acc[g][1] = 0ULL; }

#pragma unroll 4
        for (int k = 0; k < HDIM; ++k) {
            u64x2 ha = *(const u64x2*)(h1 + k * HPAD + m0);      // rows m0..m0+3
            const u64* wp = sW0 + (k * 32 + j) * 4;
            u64x2 w01 = *(const u64x2*)wp;
            u64x2 w23 = *(const u64x2*)(wp + 2);
            ffma2(acc[0][0], ha.x, w01.x); ffma2(acc[0][1], ha.y, w01.x);
            ffma2(acc[1][0], ha.x, w01.y); ffma2(acc[1][1], ha.y, w01.y);
            ffma2(acc[2][0], ha.x, w23.x); ffma2(acc[2][1], ha.y, w23.x);
            ffma2(acc[3][0], ha.x, w23.y); ffma2(acc[3][1], ha.y, w23.y);
        }

        float hn[4];
#pragma unroll
        for (int p = 0; p < 2; ++p) {
            float2 iv = unpack2(acc[0][p]);
            float2 fv = unpack2(acc[1][p]);
            float2 gv = unpack2(acc[2][p]);
            float2 ov = unpack2(acc[3][p]);
            iv.x += xr[0][2 * p]; iv.y += xr[0][2 * p + 1];
            fv.x += xr[1][2 * p]; fv.y += xr[1][2 * p + 1];
            gv.x += xr[2][2 * p]; gv.y += xr[2][2 * p + 1];
            ov.x += xr[3][2 * p]; ov.y += xr[3][2 * p + 1];
            float ca = sigf(fv.x) * c1[2 * p]     + sigf(iv.x) * tanhf_(gv.x);
            float cb = sigf(fv.y) * c1[2 * p + 1] + sigf(iv.y) * tanhf_(gv.y);
            c1[2 * p] = ca; c1[2 * p + 1] = cb;
            hn[2 * p]     = sigf(ov.x) * tanhf_(ca);
            hn[2 * p + 1] = sigf(ov.y) * tanhf_(cb);
        }
        __syncwarp();
        *(float4*)(h1 + j * HPAD + m0) = make_float4(hn[0], hn[1], hn[2], hn[3]);
        __syncwarp();

        // ---- layer 2: acc = h1_new @ Wih1^T + h2 @ Whh1^T ----
#pragma unroll
        for (int g = 0; g < 4; ++g) { acc[g][0] = 0ULL; acc[g][1] = 0ULL; }

#pragma unroll 4
        for (int k = 0; k < HDIM; ++k) {
            u64x2 ha = *(const u64x2*)(h1 + k * HPAD + m0);
            u64x2 hb = *(const u64x2*)(h2 + k * HPAD + m0);
            const u64* wpa = sW1 + (k * 32 + j) * 4;
            const u64* wpb = sW2 + (k * 32 + j) * 4;
            u64x2 wa01 = *(const u64x2*)wpa;
            u64x2 wa23 = *(const u64x2*)(wpa + 2);
            u64x2 wb01 = *(const u64x2*)wpb;
            u64x2 wb23 = *(const u64x2*)(wpb + 2);
            ffma2(acc[0][0], ha.x, wa01.x); ffma2(acc[0][1], ha.y, wa01.x);
            ffma2(acc[1][0], ha.x, wa01.y); ffma2(acc[1][1], ha.y, wa01.y);
            ffma2(acc[2][0], ha.x, wa23.x); ffma2(acc[2][1], ha.y, wa23.x);
            ffma2(acc[3][0], ha.x, wa23.y); ffma2(acc[3][1], ha.y, wa23.y);
            ffma2(acc[0][0], hb.x, wb01.x); ffma2(acc[0][1], hb.y, wb01.x);
            ffma2(acc[1][0], hb.x, wb01.y); ffma2(acc[1][1], hb.y, wb01.y);
            ffma2(acc[2][0], hb.x, wb23.x); ffma2(acc[2][1], hb.y, wb23.x);
            ffma2(acc[3][0], hb.x, wb23.y); ffma2(acc[3][1], hb.y, wb23.y);
        }

#pragma unroll
        for (int p = 0; p < 2; ++p) {
            float2 iv = unpack2(acc[0][p]);
            float2 fv = unpack2(acc[1][p]);
            float2 gv = unpack2(acc[2][p]);
            float2 ov = unpack2(acc[3][p]);
            float ca = sigf(fv.x) * c2[2 * p]     + sigf(iv.x) * tanhf_(gv.x);
            float cb = sigf(fv.y) * c2[2 * p + 1] + sigf(iv.y) * tanhf_(gv.y);
            c2[2 * p] = ca; c2[2 * p + 1] = cb;
            hn[2 * p]     = sigf(ov.x) * tanhf_(ca);
            hn[2 * p + 1] = sigf(ov.y) * tanhf_(cb);
        }
        __syncwarp();
        *(float4*)(h2 + j * HPAD + m0) = make_float4(hn[0], hn[1], hn[2], hn[3]);
        __syncwarp();
    }
    __syncthreads();

    // ---- epilogue: y = relu(c_n @ W1^T + b1) @ W2^T ----
    float* cs = (float*)smraw;                     // overlay on weight region
#pragma unroll
    for (int q = 0; q < 4; ++q) {
        cs[(m0 + q) * 33 + j]      = c1[q];
        cs[(64 + m0 + q) * 33 + j] = c2[q];
    }
    __syncthreads();

    if (tid < 128) {
        int L = tid >> 6, m = tid & 63;
        const float* crow = &cs[(L * 64 + m) * 33];
        float y = 0.0f;
#pragma unroll
        for (int u = 0; u < 16; ++u) {
            float s = __ldg(&b1[u]);
#pragma unroll
            for (int q = 0; q < 32; ++q) s += crow[q] * __ldg(&W1[u * 32 + q]);
            y += fmaxf(s, 0.0f) * __ldg(&W2[u]);
        }
        out[L * B_TOTAL + blk * 64 + m] = y;
    }
}

extern "C" void kernel_launch(void* const* d_in, const int* in_sizes, int n_in,
                              void* d_out, int out_size) {
    const float* x    = (const float*)d_in[0];
    const float* Wih0 = (const float*)d_in[1];
    const float* Whh0 = (const float*)d_in[2];
    const float* Wih1 = (const float*)d_in[3];
    const float* Whh1 = (const float*)d_in[4];
    const float* W1   = (const float*)d_in[5];
    const float* b1   = (const float*)d_in[6];
    const float* W2   = (const float*)d_in[7];
    float* out        = (float*)d_out;

    cudaFuncSetAttribute(xg_kernel, cudaFuncAttributeMaxDynamicSharedMemorySize, A_SMEM_BYTES);
    cudaFuncSetAttribute(lstm_rec_kernel, cudaFuncAttributeMaxDynamicSharedMemorySize, B_SMEM_BYTES);

    int dev = 0;
    cudaGetDevice(&dev);
    int sms = 148;
    cudaDeviceGetAttribute(&sms, cudaDevAttrMultiProcessorCount, dev);
    if (sms < 1) sms = 148;
    if (sms > A_ITEMS) sms = A_ITEMS;

    xg_kernel<<<sms, A_THREADS, A_SMEM_BYTES>>>(x, Wih0);
    lstm_rec_kernel<<<NBLK, B_THREADS, B_SMEM_BYTES>>>(Whh0, Wih1, Whh1, W1, b1, W2, out);
}

// round 7
// speedup vs baseline: 1.8042x; 1.8042x over previous
#include <cuda_runtime.h>
#include <stdint.h>
#include <math.h>

// Problem constants
#define B_TOTAL 8192
#define T_STEPS 60
#define F_IN    158
#define HDIM    32
#define G4      128
#define NBLK    128                    // 64-row batch tiles
#define KP      79                     // k-pairs covering F_IN
#define TPAIRS  30                     // timestep pairs

typedef unsigned long long u64;
typedef ulonglong2 u64x2;

// 251.7 MB scratch: xg[tile][m(64)][n(128)], tile = t*NBLK + blk
__device__ __align__(256) float g_xg[(size_t)T_STEPS * NBLK * 64 * G4];

// ---------------- helpers ----------------
__device__ __forceinline__ void ffma2(u64 &acc, u64 a, u64 b) {
    asm("fma.rn.f32x2 %0, %1, %2, %0;" : "+l"(acc) : "l"(a), "l"(b));
}
__device__ __forceinline__ u64 pack2s(float x) {
    u64 r; asm("mov.b64 %0, {%1, %1};" : "=l"(r) : "f"(x)); return r;
}
__device__ __forceinline__ float2 unpack2(u64 v) {
    float2 r; asm("mov.b64 {%0, %1}, %2;" : "=f"(r.x), "=f"(r.y) : "l"(v)); return r;
}
__device__ __forceinline__ float tanha(float x) {
    float y; asm("tanh.approx.f32 %0, %1;" : "=f"(y) : "f"(x)); return y;
}
__device__ __forceinline__ float sigf(float x) {      // 0.5*tanh(x/2)+0.5
    return fmaf(0.5f, tanha(0.5f * x), 0.5f);
}
__device__ __forceinline__ void cp_async16(uint32_t dst, const void* src) {
    asm volatile("cp.async.cg.shared.global [%0], [%1], 16;" :: "r"(dst), "l"(src));
}
__device__ __forceinline__ void cp_commit() { asm volatile("cp.async.commit_group;"); }
__device__ __forceinline__ void cp_wait1()  { asm volatile("cp.async.wait_group 1;" ::: "memory"); }

// =======================================================================
// Kernel A: xg = x @ W_ih0^T, timestep-pair items, 512 threads.
//   item = (tp, blk, half): 32 batch rows, timesteps 2tp, 2tp+1.
//   Weight layout: sWp[kp*128 + n] = (W[n][2kp], W[n][2kp+1]) u64,
//   lane-contiguous -> conflict-free LDS.64.
// =======================================================================
#define A_THREADS 512
#define A_ROWS    32
#define A_XROW    320
#define A_XBUF    (A_ROWS * A_XROW)        // 10240 floats
#define A_ITEMS   (TPAIRS * NBLK * 2)      // 7680
#define A_SW_U64  (KP * G4)                // 10112 u64 = 80896 B
#define A_SMEM_BYTES (A_SW_U64 * 8 + 2 * A_XBUF * 4)   // 162816 B

__device__ __forceinline__ void a_copy_item(const float* __restrict__ x,
                                            int item, float* xbuf, int tid) {
    int tp = item >> 8;
    int rem = item & 255;
    int blk = rem >> 1, half = rem & 1;
    const char* sb = (const char*)x
        + (size_t)(blk * 64 + half * 32) * (F_IN * T_STEPS * 4)
        + (size_t)tp * 1264;                       // 2*158*4 bytes, 16B aligned
    uint32_t db = (uint32_t)__cvta_generic_to_shared(xbuf);
    for (int i = tid; i < A_ROWS * KP; i += A_THREADS) {
        int r = i / KP, c = i - r * KP;            // 79 x 16B chunks = 316 floats
        cp_async16(db + r * (A_XROW * 4) + 16 * c,
                   sb + (size_t)r * (F_IN * T_STEPS * 4) + 16 * c);
    }
}

__global__ void __launch_bounds__(A_THREADS)
xg_kernel(const float* __restrict__ x, const float* __restrict__ Wih0) {
    extern __shared__ char smraw[];
    u64*   sWp = (u64*)smraw;                      // [kp][n] = (W[n][2kp],W[n][2kp+1])
    float* xb  = (float*)(smraw + A_SW_U64 * 8);   // [2][32][320]

    const int tid = threadIdx.x;
    const int lane = tid & 31, wrp = tid >> 5;
    const int r0 = wrp * 2;                        // 16 warps x 2 rows

    for (int i = tid; i < KP * G4; i += A_THREADS) {
        int kp = i >> 7, n = i & 127;
        sWp[kp * G4 + n] = *(const u64*)(Wih0 + n * F_IN + 2 * kp);
    }

    int item = blockIdx.x;
    a_copy_item(x, item, xb, tid);
    cp_commit();

    int cur = 0;
    for (; item < A_ITEMS; item += gridDim.x) {
        int nxt = item + gridDim.x;
        if (nxt < A_ITEMS) a_copy_item(x, nxt, xb + (cur ^ 1) * A_XBUF, tid);
        cp_commit();
        cp_wait1();
        __syncthreads();           // current x buffer resident, weights loaded

        const float* xbase = xb + cur * A_XBUF + r0 * A_XROW;

        u64 acc[2][4][2];          // [tile][g][row], k-parity split in the u64
#pragma unroll
        for (int ti = 0; ti < 2; ++ti)
#pragma unroll
            for (int g = 0; g < 4; ++g) { acc[ti][g][0] = 0ULL; acc[ti][g][1] = 0ULL; }

#pragma unroll 1
        for (int kp2 = 0; kp2 < 39; ++kp2) {       // kp = 2*kp2, 2*kp2+1
            const float* xk = xbase + 4 * kp2;
            u64 x0a[2], x0b[2], x1a[2], x1b[2];
#pragma unroll
            for (int q = 0; q < 2; ++q) {
                u64x2 v = *(const u64x2*)(xk + q * A_XROW);        // tile0 kp,kp+1
                x0a[q] = v.x; x0b[q] = v.y;
                x1a[q] = *(const u64*)(xk + q * A_XROW + 158);     // tile1 kp
                x1b[q] = *(const u64*)(xk + q * A_XROW + 160);     // tile1 kp+1
            }
            const u64* wp0 = sWp + (2 * kp2) * G4 + lane;
            const u64* wp1 = wp0 + G4;
#pragma unroll
            for (int g = 0; g < 4; ++g) {
                u64 wa = wp0[32 * g];              // kp,   gate g
                u64 wc = wp1[32 * g];              // kp+1, gate g
#pragma unroll
                for (int q = 0; q < 2; ++q) {
                    ffma2(acc[0][g][q], x0a[q], wa);
                    ffma2(acc[0][g][q], x0b[q], wc);
                    ffma2(acc[1][g][q], x1a[q], wa);
                    ffma2(acc[1][g][q], x1b[q], wc);
                }
            }
        }
        {   // tail kp = 78
            const float* xk = xbase + 156;
            const u64* wp = sWp + 78 * G4 + lane;
#pragma unroll
            for (int q = 0; q < 2; ++q) {
                u64 x0 = *(const u64*)(xk + q * A_XROW);
                u64 x1 = *(const u64*)(xk + q * A_XROW + 158);
#pragma unroll
                for (int g = 0; g < 4; ++g) {
                    u64 wa = wp[32 * g];
                    ffma2(acc[0][g][q], x0, wa);
                    ffma2(acc[1][g][q], x1, wa);
                }
            }
        }

        // fold k-parity halves, direct coalesced STG.32
        {
            int tp = item >> 8;
            int rem = item & 255;
            int blk = rem >> 1, half = rem & 1;
#pragma unroll
            for (int ti = 0; ti < 2; ++ti) {
                int t = 2 * tp + ti;
                float* dst = g_xg + ((size_t)t * NBLK + blk) * (64 * G4)
                                  + (size_t)(half * 32 + r0) * G4 + lane;
#pragma unroll
                for (int q = 0; q < 2; ++q)
#pragma unroll
                    for (int g = 0; g < 4; ++g) {
                        float2 v = unpack2(acc[ti][g][q]);
                        dst[q * G4 + 32 * g] = v.x + v.y;
                    }
            }
        }
        __syncthreads();           // everyone done reading xb[cur] before overwrite
        cur ^= 1;
    }
}

// =======================================================================
// Kernel B: recurrence. 256 threads, 8 rows/warp (warp-private h, no block
// barriers in loop). Non-duplicated LDS.32 weights (conflict-free) + pack
// movs; h via broadcast LDS.128; tanh.approx activations.
// =======================================================================
#define B_THREADS 256
#define HPAD 68
#define B_SW  (HDIM * G4)                      // 4096 floats per matrix
#define B_SMEM_BYTES (3 * B_SW * 4 + 2 * HDIM * HPAD * 4)   // 66560 B

__global__ void __launch_bounds__(B_THREADS)
lstm_rec_kernel(const float* __restrict__ Whh0, const float* __restrict__ Wih1,
                const float* __restrict__ Whh1, const float* __restrict__ W1,
                const float* __restrict__ b1,   const float* __restrict__ W2,
                float* __restrict__ out) {
    extern __shared__ char smraw[];
    float* sW0 = (float*)smraw;                     // Whh0 [k][128]
    float* sW1 = sW0 + B_SW;                        // Wih1
    float* sW2 = sW1 + B_SW;                        // Whh1
    float* h1  = sW2 + B_SW;                        // [32][68]
    float* h2  = h1 + HDIM * HPAD;

    const int tid = threadIdx.x;
    const int j = tid & 31, wrp = tid >> 5;
    const int m0 = wrp * 8;                         // 8 warps x 8 rows
    const int blk = blockIdx.x;

    for (int i = tid; i < HDIM * G4; i += B_THREADS) {
        int k = i >> 7, n = i & 127;
        sW0[i] = Whh0[n * HDIM + k];
        sW1[i] = Wih1[n * HDIM + k];
        sW2[i] = Whh1[n * HDIM + k];
    }
    for (int i = tid; i < 2 * HDIM * HPAD; i += B_THREADS) h1[i] = 0.0f;
    __syncthreads();

    float c1[8], c2[8];
#pragma unroll
    for (int q = 0; q < 8; ++q) { c1[q] = 0.0f; c2[q] = 0.0f; }

    for (int t = 0; t < T_STEPS; ++t) {
        // coalesced xg prefetch (consumed after the layer-1 gemm)
        const float* xt = g_xg + ((size_t)t * NBLK + blk) * (64 * G4);
        float xr[4][8];                             // [g][row]
#pragma unroll
        for (int g = 0; g < 4; ++g)
#pragma unroll
            for (int q = 0; q < 8; ++q)
                xr[g][q] = __ldg(xt + (m0 + q) * G4 + j + 32 * g);

        // ---- layer 1: acc = h1 @ Whh0^T ----
        u64 acc[4][4];                              // [g][rowpair]
#pragma unroll
        for (int g = 0; g < 4; ++g)
#pragma unroll
            for (int p = 0; p < 4; ++p) acc[g][p] = 0ULL;

#pragma unroll 4
        for (int k = 0; k < HDIM; ++k) {
            u64x2 ha = *(const u64x2*)(h1 + k * HPAD + m0);      // rows m0..m0+3
            u64x2 hb = *(const u64x2*)(h1 + k * HPAD + m0 + 4);  // rows m0+4..m0+7
            const float* wk = sW0 + k * G4 + j;
#pragma unroll
            for (int g = 0; g < 4; ++g) {
                u64 wv = pack2s(wk[32 * g]);
                ffma2(acc[g][0], ha.x, wv);
                ffma2(acc[g][1], ha.y, wv);
                ffma2(acc[g][2], hb.x, wv);
                ffma2(acc[g][3], hb.y, wv);
            }
        }

        float hn[8];
#pragma unroll
        for (int p = 0; p < 4; ++p) {
            float2 iv = unpack2(acc[0][p]);
            float2 fv = unpack2(acc[1][p]);
            float2 gv = unpack2(acc[2][p]);
            float2 ov = unpack2(acc[3][p]);
            iv.x += xr[0][2 * p]; iv.y += xr[0][2 * p + 1];
            fv.x += xr[1][2 * p]; fv.y += xr[1][2 * p + 1];
            gv.x += xr[2][2 * p]; gv.y += xr[2][2 * p + 1];
            ov.x += xr[3][2 * p]; ov.y += xr[3][2 * p + 1];
            float ca = sigf(fv.x) * c1[2 * p]     + sigf(iv.x) * tanha(gv.x);
            float cb = sigf(fv.y) * c1[2 * p + 1] + sigf(iv.y) * tanha(gv.y);
            c1[2 * p] = ca; c1[2 * p + 1] = cb;
            hn[2 * p]     = sigf(ov.x) * tanha(ca);
            hn[2 * p + 1] = sigf(ov.y) * tanha(cb);
        }
        __syncwarp();
        *(float4*)(h1 + j * HPAD + m0)     = make_float4(hn[0], hn[1], hn[2], hn[3]);
        *(float4*)(h1 + j * HPAD + m0 + 4) = make_float4(hn[4], hn[5], hn[6], hn[7]);
        __syncwarp();

        // ---- layer 2: acc = h1_new @ Wih1^T + h2 @ Whh1^T ----
#pragma unroll
        for (int g = 0; g < 4; ++g)
#pragma unroll
            for (int p = 0; p < 4; ++p) acc[g][p] = 0ULL;

#pragma unroll 4
        for (int k = 0; k < HDIM; ++k) {
            u64x2 ha = *(const u64x2*)(h1 + k * HPAD + m0);
            u64x2 hb = *(const u64x2*)(h1 + k * HPAD + m0 + 4);
            u64x2 ga = *(const u64x2*)(h2 + k * HPAD + m0);
            u64x2 gb = *(const u64x2*)(h2 + k * HPAD + m0 + 4);
            const float* wka = sW1 + k * G4 + j;
            const float* wkb = sW2 + k * G4 + j;
#pragma unroll
            for (int g = 0; g < 4; ++g) {
                u64 wa = pack2s(wka[32 * g]);
                u64 wb = pack2s(wkb[32 * g]);
                ffma2(acc[g][0], ha.x, wa);
                ffma2(acc[g][1], ha.y, wa);
                ffma2(acc[g][2], hb.x, wa);
                ffma2(acc[g][3], hb.y, wa);
                ffma2(acc[g][0], ga.x, wb);
                ffma2(acc[g][1], ga.y, wb);
                ffma2(acc[g][2], gb.x, wb);
                ffma2(acc[g][3], gb.y, wb);
            }
        }

#pragma unroll
        for (int p = 0; p < 4; ++p) {
            float2 iv = unpack2(acc[0][p]);
            float2 fv = unpack2(acc[1][p]);
            float2 gv = unpack2(acc[2][p]);
            float2 ov = unpack2(acc[3][p]);
            float ca = sigf(fv.x) * c2[2 * p]     + sigf(iv.x) * tanha(gv.x);
            float cb = sigf(fv.y) * c2[2 * p + 1] + sigf(iv.y) * tanha(gv.y);
            c2[2 * p] = ca; c2[2 * p + 1] = cb;
            hn[2 * p]     = sigf(ov.x) * tanha(ca);
            hn[2 * p + 1] = sigf(ov.y) * tanha(cb);
        }
        __syncwarp();
        *(float4*)(h2 + j * HPAD + m0)     = make_float4(hn[0], hn[1], hn[2], hn[3]);
        *(float4*)(h2 + j * HPAD + m0 + 4) = make_float4(hn[4], hn[5], hn[6], hn[7]);
        __syncwarp();
    }
    __syncthreads();

    // ---- epilogue: y = relu(c_n @ W1^T + b1) @ W2^T ----
    float* cs = (float*)smraw;                     // overlay on weight region
#pragma unroll
    for (int q = 0; q < 8; ++q) {
        cs[(m0 + q) * 33 + j]      = c1[q];
        cs[(64 + m0 + q) * 33 + j] = c2[q];
    }
    __syncthreads();

    if (tid < 128) {
        int L = tid >> 6, m = tid & 63;
        const float* crow = &cs[(L * 64 + m) * 33];
        float y = 0.0f;
#pragma unroll
        for (int u = 0; u < 16; ++u) {
            float s = __ldg(&b1[u]);
#pragma unroll
            for (int q = 0; q < 32; ++q) s += crow[q] * __ldg(&W1[u * 32 + q]);
            y += fmaxf(s, 0.0f) * __ldg(&W2[u]);
        }
        out[L * B_TOTAL + blk * 64 + m] = y;
    }
}

extern "C" void kernel_launch(void* const* d_in, const int* in_sizes, int n_in,
                              void* d_out, int out_size) {
    const float* x    = (const float*)d_in[0];
    const float* Wih0 = (const float*)d_in[1];
    const float* Whh0 = (const float*)d_in[2];
    const float* Wih1 = (const float*)d_in[3];
    const float* Whh1 = (const float*)d_in[4];
    const float* W1   = (const float*)d_in[5];
    const float* b1   = (const float*)d_in[6];
    const float* W2   = (const float*)d_in[7];
    float* out        = (float*)d_out;

    cudaFuncSetAttribute(xg_kernel, cudaFuncAttributeMaxDynamicSharedMemorySize, A_SMEM_BYTES);
    cudaFuncSetAttribute(lstm_rec_kernel, cudaFuncAttributeMaxDynamicSharedMemorySize, B_SMEM_BYTES);

    int dev = 0;
    cudaGetDevice(&dev);
    int sms = 148;
    cudaDeviceGetAttribute(&sms, cudaDevAttrMultiProcessorCount, dev);
    if (sms < 1) sms = 148;
    if (sms > A_ITEMS) sms = A_ITEMS;

    xg_kernel<<<sms, A_THREADS, A_SMEM_BYTES>>>(x, Wih0);
    lstm_rec_kernel<<<NBLK, B_THREADS, B_SMEM_BYTES>>>(Whh0, Wih1, Whh1, W1, b1, W2, out);
}